// round 13
// baseline (speedup 1.0000x reference)
#include <cuda_runtime.h>

#define S_GRID 28
#define SS 784            // 28*28
#define NC 80
#define BB 2
#define MAXB 50
#define PRED_C 90         // BB*5 + NC

__device__ float g_partial[4096];
__device__ int   g_count = 0;

__global__ __launch_bounds__(256) void yolo_loss_kernel(
    const float* __restrict__ pred,
    const float* __restrict__ tgt,
    float* __restrict__ out,
    int batch)
{
    const int b   = blockIdx.x;
    const int tid = threadIdx.x;

    __shared__ unsigned long long s_key[SS];   // (bits(best)<<32)|(63-t); 0 = empty
    __shared__ int      s_resp[SS];            // winning TARGET index; -1 = none
    __shared__ unsigned s_cls[SS][3];          // 80-bit class mask
    // per-target state (written in phase 1, read via s_resp in obj loop)
    __shared__ float4   s_tgbox[MAXB];         // gt: cx_rel, cy_rel, w, h
    __shared__ float4   s_tpbox[MAXB];         // responsible pred box (raw)
    __shared__ float    s_tpconf[MAXB];        // responsible pred conf
    __shared__ float    s_tbest[MAXB];         // best IoU
    __shared__ int      s_objlist[MAXB + 2];
    __shared__ int      s_nobj;
    __shared__ float    s_red[8];

    const float cell = 1.0f / 28.0f;
    const float* pb = pred + (size_t)b * SS * PRED_C;

    // ---- issue the target loads ASAP (head of dependent chain) ----
    float t0 = 0.f, t1 = 0.f, t2 = 0.f, t3 = 0.f, t4 = -1.f;
    if (tid < MAXB) {
        const float* tt = tgt + ((size_t)b * MAXB + tid) * 5;
        t4 = tt[0]; t0 = tt[1]; t1 = tt[2]; t2 = tt[3]; t3 = tt[4];
    }

    // ---- noobj conf sweep: lane-pair mapping (WIN config from R12) ----
    // task j -> cell j>>1, conf offset 4 (even) / 9 (odd). Warp covers 16
    // consecutive rows -> ~19 L1tex lines per warp-LDG instead of 32.
    // 1568 tasks = 6*256 unguarded + 32-task tail.
    float acc_noobj = 0.0f;
    {
        float v0, v1, v2, v3, v4, v5, v6 = 0.0f;
        int j0 = tid;
        v0 = __ldg(pb + (j0 >> 1) * PRED_C + ((j0 & 1) ? 9 : 4));
        int j1 = tid + 256;
        v1 = __ldg(pb + (j1 >> 1) * PRED_C + ((j1 & 1) ? 9 : 4));
        int j2 = tid + 512;
        v2 = __ldg(pb + (j2 >> 1) * PRED_C + ((j2 & 1) ? 9 : 4));
        int j3 = tid + 768;
        v3 = __ldg(pb + (j3 >> 1) * PRED_C + ((j3 & 1) ? 9 : 4));
        int j4 = tid + 1024;
        v4 = __ldg(pb + (j4 >> 1) * PRED_C + ((j4 & 1) ? 9 : 4));
        int j5 = tid + 1280;
        v5 = __ldg(pb + (j5 >> 1) * PRED_C + ((j5 & 1) ? 9 : 4));
        if (tid < 2 * SS - 1536) {
            int j6 = tid + 1536;
            v6 = __ldg(pb + (j6 >> 1) * PRED_C + ((j6 & 1) ? 9 : 4));
        }
        acc_noobj = ((v0 * v0 + v1 * v1) + (v2 * v2 + v3 * v3))
                  + ((v4 * v4 + v5 * v5) + v6 * v6);
    }

    // ---- SMEM init ----
    for (int c = tid; c < SS; c += 256) {
        s_key[c]  = 0ull;
        s_resp[c] = -1;
        s_cls[c][0] = 0u; s_cls[c][1] = 0u; s_cls[c][2] = 0u;
    }
    __syncthreads();

    // ---- phase 1: per-target precompute (float2 gather) + atomicMax race ----
    int   my_cell = -1;
    unsigned long long my_key = 0ull;
    if (tid < MAXB && t4 >= 0.0f) {
        float cx = t0, cy = t1, w = t2, h = t3;
        int ci  = min(max((int)t4, 0), NC - 1);
        int col = min((int)(cx / cell), S_GRID - 1);
        int row = min((int)(cy / cell), S_GRID - 1);
        my_cell = row * S_GRID + col;
        s_tgbox[tid] = make_float4(cx / cell - (float)col,
                                   cy / cell - (float)row, w, h);

        // pred row: 10 floats = 5 aligned float2 (360*c bytes % 8 == 0)
        const float2* pp2 =
            reinterpret_cast<const float2*>(pb + (size_t)my_cell * PRED_C);
        float2 q0 = __ldg(pp2 + 0);   // x0 y0
        float2 q1 = __ldg(pp2 + 1);   // w0 h0
        float2 q2 = __ldg(pp2 + 2);   // c0 x1
        float2 q3 = __ldg(pp2 + 3);   // y1 w1
        float2 q4 = __ldg(pp2 + 4);   // h1 c1
        float bxj[2] = {q0.x, q2.y};
        float byj[2] = {q0.y, q3.x};
        float bwj[2] = {q1.x, q3.y};
        float bhj[2] = {q1.y, q4.x};
        float bcj[2] = {q2.x, q4.y};

        float gx1 = cx - w * 0.5f, gy1 = cy - h * 0.5f;
        float gx2 = cx + w * 0.5f, gy2 = cy + h * 0.5f;
        float garea = fmaxf(gx2 - gx1, 0.0f) * fmaxf(gy2 - gy1, 0.0f);
        float iou[2];
        #pragma unroll
        for (int j = 0; j < 2; j++) {
            float px = (bxj[j] + (float)col) * cell;
            float py = (byj[j] + (float)row) * cell;
            float pw = bwj[j], ph = bhj[j];
            float px1 = px - pw * 0.5f, py1 = py - ph * 0.5f;
            float px2 = px + pw * 0.5f, py2 = py + ph * 0.5f;
            float iw = fmaxf(fminf(px2, gx2) - fmaxf(px1, gx1), 0.0f);
            float ih = fmaxf(fminf(py2, gy2) - fmaxf(py1, gy1), 0.0f);
            float inter = iw * ih;
            float uni = fmaxf(px2 - px1, 0.0f) * fmaxf(py2 - py1, 0.0f)
                      + garea - inter;
            iou[j] = inter / (uni + 1e-6f);
        }
        int r = (iou[1] > iou[0]) ? 1 : 0;         // first-index tie break
        float best = fmaxf(iou[0], iou[1]);
        s_tbest[tid]  = best;
        s_tpbox[tid]  = make_float4(bxj[r], byj[r], bwj[r], bhj[r]);
        s_tpconf[tid] = bcj[r];
        // scan semantics == first index achieving the max best per cell:
        // strictly-greater steals; equal does not. Key orders by (best, -t).
        my_key = ((unsigned long long)__float_as_uint(best) << 32)
               | (unsigned long long)(63 - tid);
        atomicMax(&s_key[my_cell], my_key);
        atomicOr(&s_cls[my_cell][ci >> 5], 1u << (ci & 31));
    }
    __syncthreads();

    // winner records its target index in the cell (unique per cell)
    if (my_key != 0ull && s_key[my_cell] == my_key)
        s_resp[my_cell] = tid;
    __syncthreads();

    // ---- deterministic compaction of object cells (warp 0 ballot scan) ----
    if (tid < 32) {
        int count = 0;
        #pragma unroll
        for (int cb = 0; cb < SS; cb += 32) {
            int c = cb + tid;
            bool p = (c < SS) && (s_resp[c] >= 0);
            unsigned m = __ballot_sync(0xffffffffu, p);
            if (p) s_objlist[count + __popc(m & ((1u << tid) - 1u))] = c;
            count += __popc(m);
        }
        if (tid == 0) s_nobj = count;
    }
    __syncthreads();
    const int nobj = s_nobj;

    float acc_obj = 0.0f, acc_coord = 0.0f, acc_cls = 0.0f;

    // ---- object cells: CIoU + obj conf + noobj correction (100% SMEM) ----
    for (int i = tid; i < nobj; i += 256) {
        int c = s_objlist[i];
        int t = s_resp[c];
        float4 p = s_tpbox[t];
        float bc = s_tpconf[t];
        acc_noobj -= bc * bc;                 // responsible box excluded
        float d = bc - s_tbest[t];
        acc_obj += d * d;

        int row = c / S_GRID, col = c % S_GRID;
        float4 g = s_tgbox[t];
        float px = (p.x + (float)col) * cell, py = (p.y + (float)row) * cell;
        float pw = fabsf(p.z), ph = fabsf(p.w);
        float gx = (g.x + (float)col) * cell, gy = (g.y + (float)row) * cell;
        float gw = g.z, gh = g.w;

        float px1 = px - pw * 0.5f, py1 = py - ph * 0.5f;
        float px2 = px + pw * 0.5f, py2 = py + ph * 0.5f;
        float gx1 = gx - gw * 0.5f, gy1 = gy - gh * 0.5f;
        float gx2 = gx + gw * 0.5f, gy2 = gy + gh * 0.5f;
        float iw = fmaxf(fminf(px2, gx2) - fmaxf(px1, gx1), 0.0f);
        float ih = fmaxf(fminf(py2, gy2) - fmaxf(py1, gy1), 0.0f);
        float inter = iw * ih;
        float ap = fmaxf(px2 - px1, 0.0f) * fmaxf(py2 - py1, 0.0f);
        float ag = fmaxf(gx2 - gx1, 0.0f) * fmaxf(gy2 - gy1, 0.0f);
        float uni = ap + ag - inter;
        float iou = inter / (uni + 1e-7f);
        float rho2 = (px - gx) * (px - gx) + (py - gy) * (py - gy);
        float cw = fmaxf(px2, gx2) - fminf(px1, gx1);
        float ch = fmaxf(py2, gy2) - fminf(py1, gy1);
        float c2 = cw * cw + ch * ch + 1e-7f;
        float dv = atanf(gw / (gh + 1e-7f)) - atanf(pw / (ph + 1e-7f));
        float v = 0.40528473456935108577f * dv * dv;   // 4/pi^2
        float alpha = v / (1.0f - iou + v + 1e-7f);
        acc_coord += 1.0f - iou + rho2 / c2 + alpha * v;
    }

    // ---- class BCE: float2-vectorized over (obj cell, class pair) ----
    // class region at byte offset 360c + 40 -> 8-byte aligned.
    for (int idx = tid; idx < nobj * (NC / 2); idx += 256) {
        int i = idx / (NC / 2);
        int j = idx - i * (NC / 2);          // classes 2j, 2j+1
        int c = s_objlist[i];
        const float2* cls2 =
            reinterpret_cast<const float2*>(pb + c * PRED_C + BB * 5);
        float2 x2 = __ldg(cls2 + j);
        int c0 = 2 * j, c1 = 2 * j + 1;
        float g0 = ((s_cls[c][c0 >> 5] >> (c0 & 31)) & 1u) ? 1.0f : 0.0f;
        float g1 = ((s_cls[c][c1 >> 5] >> (c1 & 31)) & 1u) ? 1.0f : 0.0f;
        acc_cls += fmaxf(x2.x, 0.0f) - x2.x * g0 + log1pf(__expf(-fabsf(x2.x)));
        acc_cls += fmaxf(x2.y, 0.0f) - x2.y * g1 + log1pf(__expf(-fabsf(x2.y)));
    }

    // ---- block reduction: shuffle within warp, fixed-order across warps ----
    float total = 5.0f * acc_coord + acc_obj + 0.1f * acc_noobj + acc_cls;
    #pragma unroll
    for (int off = 16; off > 0; off >>= 1)
        total += __shfl_down_sync(0xffffffffu, total, off);
    if ((tid & 31) == 0) s_red[tid >> 5] = total;
    __syncthreads();
    if (tid == 0) {
        float v = ((s_red[0] + s_red[1]) + (s_red[2] + s_red[3]))
                + ((s_red[4] + s_red[5]) + (s_red[6] + s_red[7]));
        g_partial[b] = v;
        __threadfence();
    }
    __syncthreads();

    // ---- last block performs the final deterministic reduction ----
    __shared__ int s_last;
    if (tid == 0) s_last = (atomicAdd(&g_count, 1) == batch - 1) ? 1 : 0;
    __syncthreads();
    if (s_last) {
        __shared__ float s_fin[256];
        float v = 0.0f;
        for (int i = tid; i < batch; i += 256) v += g_partial[i];
        s_fin[tid] = v;
        __syncthreads();
        #pragma unroll
        for (int k = 128; k > 0; k >>= 1) {
            if (tid < k) s_fin[tid] += s_fin[tid + k];
            __syncthreads();
        }
        if (tid == 0) {
            out[0] = s_fin[0] / (float)batch;
            g_count = 0;                        // reset for next graph replay
        }
    }
}

extern "C" void kernel_launch(void* const* d_in, const int* in_sizes, int n_in,
                              void* d_out, int out_size)
{
    const float* pred = (const float*)d_in[0];
    const float* tgt  = (const float*)d_in[1];
    int batch = in_sizes[0] / (SS * PRED_C);
    if (batch > 4096) batch = 4096;
    yolo_loss_kernel<<<batch, 256>>>(pred, tgt, (float*)d_out, batch);
}

// round 14
// speedup vs baseline: 1.0172x; 1.0172x over previous
#include <cuda_runtime.h>

#define S_GRID 28
#define SS 784            // 28*28
#define NC 80
#define BB 2
#define MAXB 50
#define PRED_C 90         // BB*5 + NC

__device__ float g_partial[4096];
__device__ int   g_count = 0;

__global__ __launch_bounds__(256) void yolo_loss_kernel(
    const float* __restrict__ pred,
    const float* __restrict__ tgt,
    float* __restrict__ out,
    int batch)
{
    const int b   = blockIdx.x;
    const int tid = threadIdx.x;

    __shared__ unsigned long long s_key[SS];   // (bits(best)<<32)|(63-t); 0 = empty
    __shared__ int      s_resp[SS];            // winning TARGET index; -1 = none
    __shared__ unsigned s_cls[SS][3];          // 80-bit class mask
    __shared__ int      s_cell[MAXB];          // -1 = invalid target
    __shared__ float    s_praw[MAXB * 10];     // staged pred rows (box part)
    __shared__ float4   s_tgbox[MAXB];         // gt: cx_rel, cy_rel, w, h
    __shared__ float4   s_tpbox[MAXB];         // responsible pred box (raw)
    __shared__ float    s_tpconf[MAXB];        // responsible pred conf
    __shared__ float    s_tbest[MAXB];         // best IoU
    __shared__ int      s_objlist[MAXB + 2];
    __shared__ int      s_nobj;
    __shared__ float    s_red[8];

    const float cell = 1.0f / 28.0f;
    const float* pb = pred + (size_t)b * SS * PRED_C;

    // ---- issue the target loads ASAP (head of dependent chain) ----
    float t0 = 0.f, t1 = 0.f, t2 = 0.f, t3 = 0.f, t4 = -1.f;
    if (tid < MAXB) {
        const float* tt = tgt + ((size_t)b * MAXB + tid) * 5;
        t4 = tt[0]; t0 = tt[1]; t1 = tt[2]; t2 = tt[3]; t3 = tt[4];
    }

    // ---- noobj conf sweep: lane-pair mapping (R12 WIN config) ----
    float acc_noobj = 0.0f;
    {
        float v0, v1, v2, v3, v4, v5, v6 = 0.0f;
        int j0 = tid;
        v0 = __ldg(pb + (j0 >> 1) * PRED_C + ((j0 & 1) ? 9 : 4));
        int j1 = tid + 256;
        v1 = __ldg(pb + (j1 >> 1) * PRED_C + ((j1 & 1) ? 9 : 4));
        int j2 = tid + 512;
        v2 = __ldg(pb + (j2 >> 1) * PRED_C + ((j2 & 1) ? 9 : 4));
        int j3 = tid + 768;
        v3 = __ldg(pb + (j3 >> 1) * PRED_C + ((j3 & 1) ? 9 : 4));
        int j4 = tid + 1024;
        v4 = __ldg(pb + (j4 >> 1) * PRED_C + ((j4 & 1) ? 9 : 4));
        int j5 = tid + 1280;
        v5 = __ldg(pb + (j5 >> 1) * PRED_C + ((j5 & 1) ? 9 : 4));
        if (tid < 2 * SS - 1536) {
            int j6 = tid + 1536;
            v6 = __ldg(pb + (j6 >> 1) * PRED_C + ((j6 & 1) ? 9 : 4));
        }
        acc_noobj = ((v0 * v0 + v1 * v1) + (v2 * v2 + v3 * v3))
                  + ((v4 * v4 + v5 * v5) + v6 * v6);
    }

    // ---- SMEM init ----
    for (int c = tid; c < SS; c += 256) {
        s_key[c]  = 0ull;
        s_resp[c] = -1;
        s_cls[c][0] = 0u; s_cls[c][1] = 0u; s_cls[c][2] = 0u;
    }

    // ---- step A: cell indices (targets only; no pred dependence) ----
    if (tid < MAXB) {
        if (t4 >= 0.0f) {
            int col = min((int)(t0 / cell), S_GRID - 1);
            int row = min((int)(t1 / cell), S_GRID - 1);
            s_cell[tid]  = row * S_GRID + col;
            s_tgbox[tid] = make_float4(t0 / cell - (float)col,
                                       t1 / cell - (float)row, t2, t3);
        } else {
            s_cell[tid] = -1;
        }
    }
    __syncthreads();

    // ---- step B: cooperative row staging (task = (target, float2 slot)) ----
    // warp covers ~6.4 rows -> ~10 L1tex lines per warp-LDG (vs 32 scattered).
    if (tid < MAXB * 5) {
        int t = tid / 5;
        int q = tid - t * 5;
        int cc = s_cell[t];
        if (cc >= 0) {
            const float2* pp2 =
                reinterpret_cast<const float2*>(pb + (size_t)cc * PRED_C);
            float2 v = __ldg(pp2 + q);
            s_praw[t * 10 + 2 * q]     = v.x;
            s_praw[t * 10 + 2 * q + 1] = v.y;
        }
    }
    __syncthreads();

    // ---- step C: per-target IoU from SMEM + atomicMax race ----
    int   my_cell = -1;
    unsigned long long my_key = 0ull;
    if (tid < MAXB && t4 >= 0.0f) {
        float cx = t0, cy = t1, w = t2, h = t3;
        int ci  = min(max((int)t4, 0), NC - 1);
        my_cell = s_cell[tid];
        int col = my_cell % S_GRID, row = my_cell / S_GRID;

        const float* pr = &s_praw[tid * 10];
        float bxj[2] = {pr[0], pr[5]};
        float byj[2] = {pr[1], pr[6]};
        float bwj[2] = {pr[2], pr[7]};
        float bhj[2] = {pr[3], pr[8]};
        float bcj[2] = {pr[4], pr[9]};

        float gx1 = cx - w * 0.5f, gy1 = cy - h * 0.5f;
        float gx2 = cx + w * 0.5f, gy2 = cy + h * 0.5f;
        float garea = fmaxf(gx2 - gx1, 0.0f) * fmaxf(gy2 - gy1, 0.0f);
        float iou[2];
        #pragma unroll
        for (int j = 0; j < 2; j++) {
            float px = (bxj[j] + (float)col) * cell;
            float py = (byj[j] + (float)row) * cell;
            float pw = bwj[j], ph = bhj[j];
            float px1 = px - pw * 0.5f, py1 = py - ph * 0.5f;
            float px2 = px + pw * 0.5f, py2 = py + ph * 0.5f;
            float iw = fmaxf(fminf(px2, gx2) - fmaxf(px1, gx1), 0.0f);
            float ih = fmaxf(fminf(py2, gy2) - fmaxf(py1, gy1), 0.0f);
            float inter = iw * ih;
            float uni = fmaxf(px2 - px1, 0.0f) * fmaxf(py2 - py1, 0.0f)
                      + garea - inter;
            iou[j] = inter / (uni + 1e-6f);
        }
        int r = (iou[1] > iou[0]) ? 1 : 0;         // first-index tie break
        float best = fmaxf(iou[0], iou[1]);
        s_tbest[tid]  = best;
        s_tpbox[tid]  = make_float4(bxj[r], byj[r], bwj[r], bhj[r]);
        s_tpconf[tid] = bcj[r];
        // scan semantics == first index achieving the max best per cell
        my_key = ((unsigned long long)__float_as_uint(best) << 32)
               | (unsigned long long)(63 - tid);
        atomicMax(&s_key[my_cell], my_key);
        atomicOr(&s_cls[my_cell][ci >> 5], 1u << (ci & 31));
    }
    __syncthreads();

    // winner records its target index in the cell (unique per cell)
    if (my_key != 0ull && s_key[my_cell] == my_key)
        s_resp[my_cell] = tid;
    __syncthreads();

    // ---- deterministic compaction of object cells (warp 0 ballot scan) ----
    if (tid < 32) {
        int count = 0;
        #pragma unroll
        for (int cb = 0; cb < SS; cb += 32) {
            int c = cb + tid;
            bool p = (c < SS) && (s_resp[c] >= 0);
            unsigned m = __ballot_sync(0xffffffffu, p);
            if (p) s_objlist[count + __popc(m & ((1u << tid) - 1u))] = c;
            count += __popc(m);
        }
        if (tid == 0) s_nobj = count;
    }
    __syncthreads();
    const int nobj = s_nobj;

    float acc_obj = 0.0f, acc_coord = 0.0f, acc_cls = 0.0f;

    // ---- object cells: CIoU + obj conf + noobj correction (100% SMEM) ----
    for (int i = tid; i < nobj; i += 256) {
        int c = s_objlist[i];
        int t = s_resp[c];
        float4 p = s_tpbox[t];
        float bc = s_tpconf[t];
        acc_noobj -= bc * bc;                 // responsible box excluded
        float d = bc - s_tbest[t];
        acc_obj += d * d;

        int row = c / S_GRID, col = c % S_GRID;
        float4 g = s_tgbox[t];
        float px = (p.x + (float)col) * cell, py = (p.y + (float)row) * cell;
        float pw = fabsf(p.z), ph = fabsf(p.w);
        float gx = (g.x + (float)col) * cell, gy = (g.y + (float)row) * cell;
        float gw = g.z, gh = g.w;

        float px1 = px - pw * 0.5f, py1 = py - ph * 0.5f;
        float px2 = px + pw * 0.5f, py2 = py + ph * 0.5f;
        float gx1 = gx - gw * 0.5f, gy1 = gy - gh * 0.5f;
        float gx2 = gx + gw * 0.5f, gy2 = gy + gh * 0.5f;
        float iw = fmaxf(fminf(px2, gx2) - fmaxf(px1, gx1), 0.0f);
        float ih = fmaxf(fminf(py2, gy2) - fmaxf(py1, gy1), 0.0f);
        float inter = iw * ih;
        float ap = fmaxf(px2 - px1, 0.0f) * fmaxf(py2 - py1, 0.0f);
        float ag = fmaxf(gx2 - gx1, 0.0f) * fmaxf(gy2 - gy1, 0.0f);
        float uni = ap + ag - inter;
        float iou = inter / (uni + 1e-7f);
        float rho2 = (px - gx) * (px - gx) + (py - gy) * (py - gy);
        float cw = fmaxf(px2, gx2) - fminf(px1, gx1);
        float ch = fmaxf(py2, gy2) - fminf(py1, gy1);
        float c2 = cw * cw + ch * ch + 1e-7f;
        float dv = atanf(gw / (gh + 1e-7f)) - atanf(pw / (ph + 1e-7f));
        float v = 0.40528473456935108577f * dv * dv;   // 4/pi^2
        float alpha = v / (1.0f - iou + v + 1e-7f);
        acc_coord += 1.0f - iou + rho2 / c2 + alpha * v;
    }

    // ---- class BCE: float2-vectorized over (obj cell, class pair) ----
    for (int idx = tid; idx < nobj * (NC / 2); idx += 256) {
        int i = idx / (NC / 2);
        int j = idx - i * (NC / 2);          // classes 2j, 2j+1
        int c = s_objlist[i];
        const float2* cls2 =
            reinterpret_cast<const float2*>(pb + c * PRED_C + BB * 5);
        float2 x2 = __ldg(cls2 + j);
        int c0 = 2 * j, c1 = 2 * j + 1;
        float g0 = ((s_cls[c][c0 >> 5] >> (c0 & 31)) & 1u) ? 1.0f : 0.0f;
        float g1 = ((s_cls[c][c1 >> 5] >> (c1 & 31)) & 1u) ? 1.0f : 0.0f;
        acc_cls += fmaxf(x2.x, 0.0f) - x2.x * g0 + log1pf(__expf(-fabsf(x2.x)));
        acc_cls += fmaxf(x2.y, 0.0f) - x2.y * g1 + log1pf(__expf(-fabsf(x2.y)));
    }

    // ---- block reduction: shuffle within warp, fixed-order across warps ----
    float total = 5.0f * acc_coord + acc_obj + 0.1f * acc_noobj + acc_cls;
    #pragma unroll
    for (int off = 16; off > 0; off >>= 1)
        total += __shfl_down_sync(0xffffffffu, total, off);
    if ((tid & 31) == 0) s_red[tid >> 5] = total;
    __syncthreads();
    if (tid == 0) {
        float v = ((s_red[0] + s_red[1]) + (s_red[2] + s_red[3]))
                + ((s_red[4] + s_red[5]) + (s_red[6] + s_red[7]));
        g_partial[b] = v;
        __threadfence();
    }
    __syncthreads();

    // ---- last block performs the final deterministic reduction ----
    __shared__ int s_last;
    if (tid == 0) s_last = (atomicAdd(&g_count, 1) == batch - 1) ? 1 : 0;
    __syncthreads();
    if (s_last) {
        __shared__ float s_fin[256];
        float v = 0.0f;
        for (int i = tid; i < batch; i += 256) v += g_partial[i];
        s_fin[tid] = v;
        __syncthreads();
        #pragma unroll
        for (int k = 128; k > 0; k >>= 1) {
            if (tid < k) s_fin[tid] += s_fin[tid + k];
            __syncthreads();
        }
        if (tid == 0) {
            out[0] = s_fin[0] / (float)batch;
            g_count = 0;                        // reset for next graph replay
        }
    }
}

extern "C" void kernel_launch(void* const* d_in, const int* in_sizes, int n_in,
                              void* d_out, int out_size)
{
    const float* pred = (const float*)d_in[0];
    const float* tgt  = (const float*)d_in[1];
    int batch = in_sizes[0] / (SS * PRED_C);
    if (batch > 4096) batch = 4096;
    yolo_loss_kernel<<<batch, 256>>>(pred, tgt, (float*)d_out, batch);
}